// round 16
// baseline (speedup 1.0000x reference)
#include <cuda_runtime.h>
#include <cuda_bf16.h>

#define WSZ 7
#define NTOK 49
#define HW 448
#define NWIN 64
#define TOTW 16384
#define GRID 152

// strides (floats / b32 units)
#define XSTR 132     // fp32 A-operand, %32==4
#define QBSTR 68     // q/k bf16x2 (b32), %32==4
#define VSTR 136     // V fp32 B-operand, %32==8
#define WSTR 136     // %32==8
#define LSTR 60      // %32==28: banks 28*gid+tig distinct -> conflict-free A frags
#define LSH  (49 * LSTR)

#define XS0_OFF 0                       // [49][132] buf0
#define XS1_OFF (XS0_OFF + 49 * XSTR)   // 6468  buf1
#define QB_OFF  (XS1_OFF + 49 * XSTR)   // 12936 [49][68] b32
#define KB_OFF  (QB_OFF + 49 * QBSTR)   // 16268 [56][68] b32 (rows 49-55 zero)
#define VS_OFF  (KB_OFF + 56 * QBSTR)   // 20076 [56][136] (rows 49-55 zero)
#define WS_OFF  (VS_OFF + 56 * VSTR)    // 27692 [128][136]
#define LS_OFF  (WS_OFF + 128 * WSTR)   // 45100 [4][49][60]
#define BQ_OFF  (LS_OFF + 4 * LSH)      // 56860
#define BP_OFF  (BQ_OFF + 384)          // 57244
#define BT_OFF  (BP_OFF + 128)          // 57372
#define SMEM_FLOATS (BT_OFF + 16)       // 57388
#define SMEM_BYTES  (SMEM_FLOATS * 4)   // 229552 (<= 232448)

__device__ __forceinline__ float f2tf(float f) {
    unsigned u;
    asm("cvt.rna.tf32.f32 %0, %1;" : "=r"(u) : "f"(f));
    return __uint_as_float(u);
}

__device__ __forceinline__ unsigned packbf(float a, float b) {
    unsigned lo = (unsigned)__bfloat16_as_ushort(__float2bfloat16_rn(a));
    unsigned hi = (unsigned)__bfloat16_as_ushort(__float2bfloat16_rn(b));
    return lo | (hi << 16);
}

__device__ __forceinline__ void mma8(float* c, const unsigned* a, unsigned b0, unsigned b1) {
    asm volatile(
        "mma.sync.aligned.m16n8k8.row.col.f32.tf32.tf32.f32 "
        "{%0,%1,%2,%3},{%4,%5,%6,%7},{%8,%9},{%0,%1,%2,%3};\n"
        : "+f"(c[0]), "+f"(c[1]), "+f"(c[2]), "+f"(c[3])
        : "r"(a[0]), "r"(a[1]), "r"(a[2]), "r"(a[3]), "r"(b0), "r"(b1));
}

__device__ __forceinline__ void mma16(float* c, const unsigned* a, unsigned b0, unsigned b1) {
    asm volatile(
        "mma.sync.aligned.m16n8k16.row.col.f32.bf16.bf16.f32 "
        "{%0,%1,%2,%3},{%4,%5,%6,%7},{%8,%9},{%0,%1,%2,%3};\n"
        : "+f"(c[0]), "+f"(c[1]), "+f"(c[2]), "+f"(c[3])
        : "r"(a[0]), "r"(a[1]), "r"(a[2]), "r"(a[3]), "r"(b0), "r"(b1));
}

#define U(x) __float_as_uint(x)
#define BSYNC(b, n)  asm volatile("bar.sync %0, %1;"   :: "r"(b), "r"(n) : "memory")
#define BARV(b, n)   asm volatile("bar.arrive %0, %1;" :: "r"(b), "r"(n) : "memory")
#define CPA_COMMIT() asm volatile("cp.async.commit_group;" ::: "memory")
#define CPA_WAIT0()  asm volatile("cp.async.wait_group 0;" ::: "memory")

__global__ __launch_bounds__(512, 1)
void win_attn_ws_kernel(
    const float* __restrict__ x,
    const float* __restrict__ w_qkv,
    const float* __restrict__ b_qkv,
    const float* __restrict__ w_proj,
    const float* __restrict__ b_proj,
    const float* __restrict__ bias_table,
    float* __restrict__ out)
{
    extern __shared__ float sm[];
    unsigned* Qb  = (unsigned*)(sm + QB_OFF);
    unsigned* Kb  = (unsigned*)(sm + KB_OFF);
    float*    Vs  = sm + VS_OFF;
    float*    Wsm = sm + WS_OFF;
    float*    Ls  = sm + LS_OFF;
    float*    BQ  = sm + BQ_OFF;
    float*    BP  = sm + BP_OFF;
    float*    BT  = sm + BT_OFF;

    const int tid = threadIdx.x;
    const int bid = blockIdx.x;

    const int tx  = tid & 31;
    const int ty  = tid >> 5;        // warp 0..15
    const int gid = tx >> 2;         // 0..7
    const int tig = tx & 3;          // 0..3

    // Phase-1 GEMM tiling (warps 0-7): 2 M-groups x 4 N-groups, 32x32 warp tiles
    const int mg = (ty >> 2) & 1;
    const int ng = ty & 3;
    int r1r[2][2], r1l[2][2];
    #pragma unroll
    for (int mt = 0; mt < 2; ++mt) {
        r1r[mt][0] = mg * 32 + mt * 16 + gid;
        r1r[mt][1] = r1r[mt][0] + 8;
        r1l[mt][0] = (r1r[mt][0] > 48) ? 48 : r1r[mt][0];
        r1l[mt][1] = (r1r[mt][1] > 48) ? 48 : r1r[mt][1];
    }

    // Phase-3 tiling (all 16 warps): 4M x 4N, warp tile 16x32 (as before)
    const int wyA = ty >> 2;
    const int wxA = ty & 3;
    const int rA0 = wyA * 16 + gid;
    const int rA1 = rA0 + 8;
    const int lA0 = (rA0 > 48) ? 48 : rA0;
    const int lA1 = (rA1 > 48) ? 48 : rA1;

    // 2c tiling: head = ty>>2, 4 warps/head (2M x 2N)
    const int hB  = ty >> 2;
    const int wy2 = (ty >> 1) & 1;
    const int wx2 = ty & 1;
    const int m0B = wy2 * 32;

    // 2a tiling (warps 8-15): 2 warps/head, warp tile 32x56
    const int w2  = ty - 8;          // 0..7 (only valid for ty>=8)
    const int hB2 = w2 >> 1;         // head 0..3
    const int hf2 = w2 & 1;          // M half
    const int m02 = hf2 * 32;

    // ---- one-time prologue ----
    if (tid < 16) BT[tid] = (tid < 13) ? bias_table[tid] : 0.f;
    if (tid < 384) BQ[tid] = b_qkv[tid];
    if (tid >= 384 && tid < 512) BP[tid - 384] = b_proj[tid - 384];
    for (int idx = tid; idx < 7 * 128; idx += 512) {
        int r = 49 + (idx >> 7), c = idx & 127;
        Vs[r * VSTR + c] = 0.f;
    }
    for (int idx = tid; idx < 7 * QBSTR; idx += 512) {
        Kb[49 * QBSTR + idx] = 0u;
    }

    // prefetch x for first window into buffer 0 (all threads)
    {
        int w = bid;
        int bz = w >> 12, rm = w & 4095, wh = rm >> 6, ww = rm & 63;
        const float* xb = x + (((long)bz * HW + wh * WSZ) * HW + ww * WSZ) * 128;
        unsigned xu = (unsigned)__cvta_generic_to_shared(sm + XS0_OFF);
        for (int idx = tid; idx < NTOK * 32; idx += 512) {
            int n = idx >> 5, c4 = idx & 31;
            int i = n / 7, j = n - i * 7;
            const float* src = xb + ((long)i * HW + j) * 128 + c4 * 4;
            asm volatile("cp.async.cg.shared.global [%0], [%1], 16;"
                :: "r"(xu + (unsigned)((n * XSTR + c4 * 4) * 4)), "l"(src));
        }
        CPA_COMMIT();
    }

    const float scale = 0.17677669529663687f;   // 1/sqrt(32)

    int it = 0;
    for (int w = bid; w < TOTW; w += GRID, ++it) {
        const int bz = w >> 12, rm = w & 4095, wh = rm >> 6, ww = rm & 63;
        float* Xs = sm + ((it & 1) ? XS1_OFF : XS0_OFF);

        CPA_WAIT0();
        __syncthreads();

        if (ty < 8) {
            // ======== GEMM group: QKV, 3 passes, 32x32 warp tiles ========
            for (int t = 0; t < 3; ++t) {
                if (t) BSYNC(5, 256);        // prior pass's Wsm reads done
                // load W tile (256 threads, 4096 float4)
                #pragma unroll 4
                for (int p = 0; p < 16; ++p) {
                    int idx = tid + 256 * p;
                    int k = idx >> 5, c4 = idx & 31;
                    float4 g = *(const float4*)(w_qkv + (long)k * 384 + t * 128 + c4 * 4);
                    g.x = f2tf(g.x); g.y = f2tf(g.y); g.z = f2tf(g.z); g.w = f2tf(g.w);
                    *(float4*)(Wsm + k * WSTR + c4 * 4) = g;
                }
                BSYNC(5, 256);               // W visible

                float c[2][4][4];
                #pragma unroll
                for (int mt = 0; mt < 2; ++mt)
                    #pragma unroll
                    for (int i = 0; i < 4; ++i)
                        { c[mt][i][0]=0.f; c[mt][i][1]=0.f; c[mt][i][2]=0.f; c[mt][i][3]=0.f; }

                #pragma unroll 4
                for (int kk = 0; kk < 16; ++kk) {
                    int k0 = kk * 8;
                    unsigned a[2][4];
                    #pragma unroll
                    for (int mt = 0; mt < 2; ++mt) {
                        a[mt][0] = U(Xs[r1l[mt][0] * XSTR + k0 + tig]);
                        a[mt][1] = U(Xs[r1l[mt][1] * XSTR + k0 + tig]);
                        a[mt][2] = U(Xs[r1l[mt][0] * XSTR + k0 + tig + 4]);
                        a[mt][3] = U(Xs[r1l[mt][1] * XSTR + k0 + tig + 4]);
                    }
                    #pragma unroll
                    for (int nt = 0; nt < 4; ++nt) {
                        int nb = ng * 32 + nt * 8 + gid;
                        unsigned b0 = U(Wsm[(k0 + tig) * WSTR + nb]);
                        unsigned b1 = U(Wsm[(k0 + tig + 4) * WSTR + nb]);
                        mma8(c[0][nt], a[0], b0, b1);
                        mma8(c[1][nt], a[1], b0, b1);
                    }
                }
                // epilogue
                #pragma unroll
                for (int mt = 0; mt < 2; ++mt) {
                    int r0 = r1r[mt][0], r1 = r1r[mt][1];
                    #pragma unroll
                    for (int nt = 0; nt < 4; ++nt) {
                        int col8 = ng * 32 + nt * 8 + 2 * tig;
                        float bb0 = BQ[t * 128 + col8], bb1 = BQ[t * 128 + col8 + 1];
                        float v00 = c[mt][nt][0] + bb0, v01 = c[mt][nt][1] + bb1;
                        float v10 = c[mt][nt][2] + bb0, v11 = c[mt][nt][3] + bb1;
                        if (t < 2) {
                            unsigned* dst = (t == 0) ? Qb : Kb;
                            int bcol = ng * 16 + nt * 4 + tig;
                            if (r0 < NTOK) dst[r0 * QBSTR + bcol] = packbf(v00, v01);
                            if (r1 < NTOK) dst[r1 * QBSTR + bcol] = packbf(v10, v11);
                        } else {
                            if (r0 < NTOK) {
                                float2 v; v.x = f2tf(v00); v.y = f2tf(v01);
                                *(float2*)(Vs + r0 * VSTR + col8) = v;
                            }
                            if (r1 < NTOK) {
                                float2 v; v.x = f2tf(v10); v.y = f2tf(v11);
                                *(float2*)(Vs + r1 * VSTR + col8) = v;
                            }
                        }
                    }
                }
                if (t == 1) BARV(6, 512);    // Q,K ready -> release attention group
            }
            BARV(7, 512);                     // V ready, Wsm free
        } else {
            // ======== Attention front-end group (warps 8-15) ========
            const int tid2 = tid - 256;       // 0..255

            // issue cp.async prefetch of NEXT window's x into the other buffer
            {
                int wn = w + GRID;
                if (wn < TOTW) {
                    int bzn = wn >> 12, rmn = wn & 4095, whn = rmn >> 6, wwn = rmn & 63;
                    const float* xb = x + (((long)bzn * HW + whn * WSZ) * HW + wwn * WSZ) * 128;
                    float* Xn = sm + ((it & 1) ? XS0_OFF : XS1_OFF);
                    unsigned xu = (unsigned)__cvta_generic_to_shared(Xn);
                    for (int idx = tid2; idx < NTOK * 32; idx += 256) {
                        int n = idx >> 5, c4 = idx & 31;
                        int i = n / 7, j = n - i * 7;
                        const float* src = xb + ((long)i * HW + j) * 128 + c4 * 4;
                        asm volatile("cp.async.cg.shared.global [%0], [%1], 16;"
                            :: "r"(xu + (unsigned)((n * XSTR + c4 * 4) * 4)), "l"(src));
                    }
                }
                CPA_COMMIT();
            }

            BSYNC(6, 512);                    // wait Q,K

            // ---- 2a: logits (2 warps/head; warp tile M=32 x N=56, bf16 k16) ----
            float* Lh = Ls + hB2 * LSH;
            {
                const int qb = hB2 * 16;
                const int la0 = m02 + gid;
                const int la1 = m02 + 8 + gid;
                int la2 = m02 + 16 + gid; if (la2 > 48) la2 = 48;
                int la3 = m02 + 24 + gid; if (la3 > 48) la3 = 48;

                float c[2][7][4];
                #pragma unroll
                for (int mt = 0; mt < 2; ++mt)
                    #pragma unroll
                    for (int i = 0; i < 7; ++i)
                        { c[mt][i][0]=0.f; c[mt][i][1]=0.f; c[mt][i][2]=0.f; c[mt][i][3]=0.f; }

                #pragma unroll
                for (int s = 0; s < 2; ++s) {
                    int k0 = s * 8;
                    unsigned a0[4], a1[4];
                    a0[0] = Qb[la0 * QBSTR + qb + k0 + tig];
                    a0[1] = Qb[la1 * QBSTR + qb + k0 + tig];
                    a0[2] = Qb[la0 * QBSTR + qb + k0 + tig + 4];
                    a0[3] = Qb[la1 * QBSTR + qb + k0 + tig + 4];
                    a1[0] = Qb[la2 * QBSTR + qb + k0 + tig];
                    a1[1] = Qb[la3 * QBSTR + qb + k0 + tig];
                    a1[2] = Qb[la2 * QBSTR + qb + k0 + tig + 4];
                    a1[3] = Qb[la3 * QBSTR + qb + k0 + tig + 4];
                    #pragma unroll
                    for (int nt = 0; nt < 7; ++nt) {
                        int nb = nt * 8 + gid;        // <= 55, rows 49-55 zero
                        unsigned b0 = Kb[nb * QBSTR + qb + k0 + tig];
                        unsigned b1 = Kb[nb * QBSTR + qb + k0 + tig + 4];
                        mma16(c[0][nt], a0, b0, b1);
                        mma16(c[1][nt], a1, b0, b1);
                    }
                }

                #pragma unroll
                for (int mt = 0; mt < 2; ++mt) {
                    int rs0 = m02 + mt * 16 + gid;
                    int rs1 = rs0 + 8;
                    int rn0 = rs0 / 7, cn0 = rs0 - rn0 * 7;
                    int rn1 = rs1 / 7, cn1 = rs1 - rn1 * 7;
                    #pragma unroll
                    for (int nt = 0; nt < 7; ++nt) {
                        int col  = nt * 8 + 2 * tig;
                        int col1 = col + 1;
                        int rm0 = col / 7,  cm0 = col  - rm0 * 7;
                        int rm1 = col1 / 7, cm1 = col1 - rm1 * 7;
                        if (rs0 < NTOK) {
                            float2 v;
                            v.x = (col  < NTOK) ? c[mt][nt][0] * scale + BT[rn0 - rm0 + 6] + BT[cn0 - cm0 + 6] : 0.f;
                            v.y = (col1 < NTOK) ? c[mt][nt][1] * scale + BT[rn0 - rm1 + 6] + BT[cn0 - cm1 + 6] : 0.f;
                            *(float2*)(Lh + rs0 * LSTR + col) = v;
                        }
                        if (rs1 < NTOK) {
                            float2 v;
                            v.x = (col  < NTOK) ? c[mt][nt][2] * scale + BT[rn1 - rm0 + 6] + BT[cn1 - cm0 + 6] : 0.f;
                            v.y = (col1 < NTOK) ? c[mt][nt][3] * scale + BT[rn1 - rm1 + 6] + BT[cn1 - cm1 + 6] : 0.f;
                            *(float2*)(Lh + rs1 * LSTR + col) = v;
                        }
                    }
                }
            }
            BSYNC(hB2 + 1, 64);               // head pair: 2a done

            // ---- 2b: max-free softmax (this head's rows, 2 warps) ----
            for (int row = hf2; row < NTOK; row += 2) {
                float e0 = __expf(Lh[row * LSTR + tx]);
                float e1 = (tx + 32 < NTOK) ? __expf(Lh[row * LSTR + tx + 32]) : 0.f;
                float s = e0 + e1;
                #pragma unroll
                for (int o = 16; o > 0; o >>= 1)
                    s += __shfl_xor_sync(0xffffffffu, s, o);
                float inv = 1.0f / s;
                Lh[row * LSTR + tx] = f2tf(e0 * inv);
                if (tx + 32 < NTOK) Lh[row * LSTR + tx + 32] = f2tf(e1 * inv);
            }

            // load w_proj into registers (2a accumulators dead now)
            float4 wpr[16];
            #pragma unroll
            for (int p = 0; p < 16; ++p) {
                int idx = tid2 + 256 * p;
                int k = idx >> 5, c4 = idx & 31;
                wpr[p] = *(const float4*)(w_proj + (long)k * 128 + c4 * 4);
            }

            BSYNC(7, 512);                    // V ready AND Wsm free

            #pragma unroll
            for (int p = 0; p < 16; ++p) {
                int idx = tid2 + 256 * p;
                int k = idx >> 5, c4 = idx & 31;
                float4 g = wpr[p];
                g.x = f2tf(g.x); g.y = f2tf(g.y); g.z = f2tf(g.z); g.w = f2tf(g.w);
                *(float4*)(Wsm + k * WSTR + c4 * 4) = g;
            }
        }

        __syncthreads();   // V + softmax + w_proj all visible

        // ---- 2c: out_h = attn @ V (all 16 warps; 4/head; M=64 N=32 K=56) ----
        {
            float* Lh = Ls + hB * LSH;
            const int qo = hB * 32;

            const int la0 = m0B + gid;
            const int la1 = m0B + 8 + gid;
            int la2 = m0B + 16 + gid; if (la2 > 48) la2 = 48;
            int la3 = m0B + 24 + gid; if (la3 > 48) la3 = 48;

            float c[2][2][4];
            #pragma unroll
            for (int mt = 0; mt < 2; ++mt)
                #pragma unroll
                for (int i = 0; i < 2; ++i)
                    { c[mt][i][0]=0.f; c[mt][i][1]=0.f; c[mt][i][2]=0.f; c[mt][i][3]=0.f; }

            #pragma unroll
            for (int ks = 0; ks < 7; ++ks) {
                int k0 = ks * 8;
                unsigned a0[4], a1[4];
                a0[0] = U(Lh[la0 * LSTR + k0 + tig]);
                a0[1] = U(Lh[la1 * LSTR + k0 + tig]);
                a0[2] = U(Lh[la0 * LSTR + k0 + tig + 4]);
                a0[3] = U(Lh[la1 * LSTR + k0 + tig + 4]);
                a1[0] = U(Lh[la2 * LSTR + k0 + tig]);
                a1[1] = U(Lh[la3 * LSTR + k0 + tig]);
                a1[2] = U(Lh[la2 * LSTR + k0 + tig + 4]);
                a1[3] = U(Lh[la3 * LSTR + k0 + tig + 4]);
                #pragma unroll
                for (int nt = 0; nt < 2; ++nt) {
                    int db = qo + wx2 * 16 + nt * 8 + gid;
                    unsigned b0 = U(Vs[(k0 + tig) * VSTR + db]);
                    unsigned b1 = U(Vs[(k0 + tig + 4) * VSTR + db]);
                    mma8(c[0][nt], a0, b0, b1);
                    mma8(c[1][nt], a1, b0, b1);
                }
            }
            #pragma unroll
            for (int mt = 0; mt < 2; ++mt) {
                int rs0 = m0B + mt * 16 + gid;
                int rs1 = rs0 + 8;
                #pragma unroll
                for (int nt = 0; nt < 2; ++nt) {
                    int col = qo + wx2 * 16 + nt * 8 + 2 * tig;
                    if (rs0 < NTOK) {
                        float2 v; v.x = f2tf(c[mt][nt][0]); v.y = f2tf(c[mt][nt][1]);
                        *(float2*)(Xs + rs0 * XSTR + col) = v;
                    }
                    if (rs1 < NTOK) {
                        float2 v; v.x = f2tf(c[mt][nt][2]); v.y = f2tf(c[mt][nt][3]);
                        *(float2*)(Xs + rs1 * XSTR + col) = v;
                    }
                }
            }
        }
        __syncthreads();

        // ---- Phase 3: proj GEMM (16 warps, 16x32 tiles), store un-windowed ----
        {
            float c[4][4];
            #pragma unroll
            for (int i = 0; i < 4; ++i) { c[i][0]=0.f; c[i][1]=0.f; c[i][2]=0.f; c[i][3]=0.f; }

            #pragma unroll 4
            for (int kk = 0; kk < 16; ++kk) {
                int k0 = kk * 8;
                unsigned a[4];
                a[0] = U(Xs[lA0 * XSTR + k0 + tig]);
                a[1] = U(Xs[lA1 * XSTR + k0 + tig]);
                a[2] = U(Xs[lA0 * XSTR + k0 + tig + 4]);
                a[3] = U(Xs[lA1 * XSTR + k0 + tig + 4]);
                #pragma unroll
                for (int nt = 0; nt < 4; ++nt) {
                    int nb = wxA * 32 + nt * 8 + gid;
                    unsigned b0 = U(Wsm[(k0 + tig) * WSTR + nb]);
                    unsigned b1 = U(Wsm[(k0 + tig + 4) * WSTR + nb]);
                    mma8(c[nt], a, b0, b1);
                }
            }

            long base0 = 0, base1 = 0;
            if (rA0 < NTOK) {
                int i = rA0 / 7, j = rA0 - (rA0 / 7) * 7;
                base0 = (((long)bz * HW + wh * WSZ + i) * HW + ww * WSZ + j) * 128;
            }
            if (rA1 < NTOK) {
                int i = rA1 / 7, j = rA1 - (rA1 / 7) * 7;
                base1 = (((long)bz * HW + wh * WSZ + i) * HW + ww * WSZ + j) * 128;
            }
            #pragma unroll
            for (int nt = 0; nt < 4; ++nt) {
                int col = wxA * 32 + nt * 8 + 2 * tig;
                float bb0 = BP[col], bb1 = BP[col + 1];
                if (rA0 < NTOK) {
                    float2 v; v.x = c[nt][0] + bb0; v.y = c[nt][1] + bb1;
                    *(float2*)(out + base0 + col) = v;
                }
                if (rA1 < NTOK) {
                    float2 v; v.x = c[nt][2] + bb0; v.y = c[nt][3] + bb1;
                    *(float2*)(out + base1 + col) = v;
                }
            }
        }
    }
}

extern "C" void kernel_launch(void* const* d_in, const int* in_sizes, int n_in,
                              void* d_out, int out_size) {
    const float* x          = (const float*)d_in[0];
    const float* w_qkv      = (const float*)d_in[1];
    const float* b_qkv      = (const float*)d_in[2];
    const float* w_proj     = (const float*)d_in[3];
    const float* b_proj     = (const float*)d_in[4];
    const float* bias_table = (const float*)d_in[5];
    float* out = (float*)d_out;
    (void)in_sizes; (void)n_in; (void)out_size;

    cudaFuncSetAttribute(win_attn_ws_kernel,
                         cudaFuncAttributeMaxDynamicSharedMemorySize, SMEM_BYTES);

    win_attn_ws_kernel<<<GRID, 512, SMEM_BYTES>>>(
        x, w_qkv, b_qkv, w_proj, b_proj, bias_table, out);
}

// round 17
// speedup vs baseline: 1.3183x; 1.3183x over previous
#include <cuda_runtime.h>
#include <cuda_bf16.h>

#define WSZ 7
#define NTOK 49
#define HW 448
#define NWIN 64
#define TOTW 16384
#define GRID 152

// strides (floats / b32 units)
#define XSTR 132     // fp32 A-operand, %32==4
#define QBSTR 68     // bf16x2 (b32) buffers, %32==4: banks 4*gid+tig / 4*n+c distinct
#define VSTR 136     // V fp32 B-operand, %32==8
#define WSTR 136     // %32==8
#define LSTR 60      // %32==28: banks 28*gid+tig distinct
#define LSH  (49 * LSTR)

#define XS0_OFF 0                       // [49][132] buf0
#define XS1_OFF (XS0_OFF + 49 * XSTR)   // 6468  buf1
#define QB_OFF  (XS1_OFF + 49 * XSTR)   // 12936 [49][68] b32
#define KB_OFF  (QB_OFF + 49 * QBSTR)   // 16268 [56][68] b32 (rows 49-55 zero)
#define VS_OFF  (KB_OFF + 56 * QBSTR)   // 20076 [56][136] (rows 49-55 zero); Xb overlays words 0..3331
#define WS_OFF  (VS_OFF + 56 * VSTR)    // 27692 [128][136] fp32 W tile (t=2, proj)
#define LS_OFF  (WS_OFF + 128 * WSTR)   // 45100 [4][49][60]; Wb overlays words 0..8703 during phase 1
#define BQ_OFF  (LS_OFF + 4 * LSH)      // 56860
#define BP_OFF  (BQ_OFF + 384)          // 57244
#define BT_OFF  (BP_OFF + 128)          // 57372
#define SMEM_FLOATS (BT_OFF + 16)       // 57388
#define SMEM_BYTES  (SMEM_FLOATS * 4)   // 229552 (<= 232448)

__device__ __forceinline__ float f2tf(float f) {
    unsigned u;
    asm("cvt.rna.tf32.f32 %0, %1;" : "=r"(u) : "f"(f));
    return __uint_as_float(u);
}

__device__ __forceinline__ unsigned packbf(float a, float b) {
    unsigned lo = (unsigned)__bfloat16_as_ushort(__float2bfloat16_rn(a));
    unsigned hi = (unsigned)__bfloat16_as_ushort(__float2bfloat16_rn(b));
    return lo | (hi << 16);
}

__device__ __forceinline__ void mma8(float* c, const unsigned* a, unsigned b0, unsigned b1) {
    asm volatile(
        "mma.sync.aligned.m16n8k8.row.col.f32.tf32.tf32.f32 "
        "{%0,%1,%2,%3},{%4,%5,%6,%7},{%8,%9},{%0,%1,%2,%3};\n"
        : "+f"(c[0]), "+f"(c[1]), "+f"(c[2]), "+f"(c[3])
        : "r"(a[0]), "r"(a[1]), "r"(a[2]), "r"(a[3]), "r"(b0), "r"(b1));
}

__device__ __forceinline__ void mma16(float* c, const unsigned* a, unsigned b0, unsigned b1) {
    asm volatile(
        "mma.sync.aligned.m16n8k16.row.col.f32.bf16.bf16.f32 "
        "{%0,%1,%2,%3},{%4,%5,%6,%7},{%8,%9},{%0,%1,%2,%3};\n"
        : "+f"(c[0]), "+f"(c[1]), "+f"(c[2]), "+f"(c[3])
        : "r"(a[0]), "r"(a[1]), "r"(a[2]), "r"(a[3]), "r"(b0), "r"(b1));
}

#define U(x) __float_as_uint(x)
#define HBAR() asm volatile("bar.sync %0, %1;" :: "r"(hB + 1), "r"(128) : "memory")
#define CPA_COMMIT() asm volatile("cp.async.commit_group;" ::: "memory")
#define CPA_WAIT0()  asm volatile("cp.async.wait_group 0;" ::: "memory")

__global__ __launch_bounds__(512, 1)
void win_attn_bfw_kernel(
    const float* __restrict__ x,
    const float* __restrict__ w_qkv,
    const float* __restrict__ b_qkv,
    const float* __restrict__ w_proj,
    const float* __restrict__ b_proj,
    const float* __restrict__ bias_table,
    float* __restrict__ out)
{
    extern __shared__ float sm[];
    unsigned* Qb  = (unsigned*)(sm + QB_OFF);
    unsigned* Kb  = (unsigned*)(sm + KB_OFF);
    float*    Vs  = sm + VS_OFF;
    unsigned* Xb  = (unsigned*)(sm + VS_OFF);   // bf16 x copy, words 0..3331 (dead by t=2)
    float*    Wsm = sm + WS_OFF;
    float*    Ls  = sm + LS_OFF;
    unsigned* Wb  = (unsigned*)(sm + LS_OFF);   // bf16 W tile [128][68], dead by phase 2
    float*    BQ  = sm + BQ_OFF;
    float*    BP  = sm + BP_OFF;
    float*    BT  = sm + BT_OFF;

    const int tid = threadIdx.x;
    const int bid = blockIdx.x;

    const int tx  = tid & 31;
    const int ty  = tid >> 5;        // warp 0..15
    const int gid = tx >> 2;         // 0..7
    const int tig = tx & 3;          // 0..3

    // Phase-1/3 tiling: 4 M-groups x 4 N-groups, warp tile 16x32
    const int wyA = ty >> 2;
    const int wxA = ty & 3;
    const int rA0 = wyA * 16 + gid;
    const int rA1 = rA0 + 8;
    const int lA0 = (rA0 > 48) ? 48 : rA0;
    const int lA1 = (rA1 > 48) ? 48 : rA1;

    // Attention tiling: head = ty>>2, 4 warps/head (2M x 2N)
    const int hB  = ty >> 2;
    const int wy2 = (ty >> 1) & 1;
    const int wx2 = ty & 1;
    const int m0B = wy2 * 32;
    const int lw  = ty & 3;

    // ---- one-time prologue ----
    if (tid < 16) BT[tid] = (tid < 13) ? bias_table[tid] : 0.f;
    if (tid < 384) BQ[tid] = b_qkv[tid];
    if (tid >= 384 && tid < 512) BP[tid - 384] = b_proj[tid - 384];
    for (int idx = tid; idx < 7 * 128; idx += 512) {
        int r = 49 + (idx >> 7), c = idx & 127;
        Vs[r * VSTR + c] = 0.f;
    }
    for (int idx = tid; idx < 7 * QBSTR; idx += 512) {
        Kb[49 * QBSTR + idx] = 0u;
    }

    // prefetch x for first window into buffer 0
    {
        int w = bid;
        int bz = w >> 12, rm = w & 4095, wh = rm >> 6, ww = rm & 63;
        const float* xb = x + (((long)bz * HW + wh * WSZ) * HW + ww * WSZ) * 128;
        unsigned xu = (unsigned)__cvta_generic_to_shared(sm + XS0_OFF);
        for (int idx = tid; idx < NTOK * 32; idx += 512) {
            int n = idx >> 5, c4 = idx & 31;
            int i = n / 7, j = n - i * 7;
            const float* src = xb + ((long)i * HW + j) * 128 + c4 * 4;
            asm volatile("cp.async.cg.shared.global [%0], [%1], 16;"
                :: "r"(xu + (unsigned)((n * XSTR + c4 * 4) * 4)), "l"(src));
        }
        CPA_COMMIT();
    }

    const float scale = 0.17677669529663687f;   // 1/sqrt(32)
    float* Lh = Ls + hB * LSH;
    const int qo = hB * 32;

    int it = 0;
    for (int w = bid; w < TOTW; w += GRID, ++it) {
        const int bz = w >> 12, rm = w & 4095, wh = rm >> 6, ww = rm & 63;
        float* Xs = sm + ((it & 1) ? XS1_OFF : XS0_OFF);

        CPA_WAIT0();
        __syncthreads();

        // issue cp.async prefetch of NEXT window's x into the other (now free) buffer
        {
            int wn = w + GRID;
            if (wn < TOTW) {
                int bzn = wn >> 12, rmn = wn & 4095, whn = rmn >> 6, wwn = rmn & 63;
                const float* xb = x + (((long)bzn * HW + whn * WSZ) * HW + wwn * WSZ) * 128;
                float* Xn = sm + ((it & 1) ? XS0_OFF : XS1_OFF);
                unsigned xu = (unsigned)__cvta_generic_to_shared(Xn);
                for (int idx = tid; idx < NTOK * 32; idx += 512) {
                    int n = idx >> 5, c4 = idx & 31;
                    int i = n / 7, j = n - i * 7;
                    const float* src = xb + ((long)i * HW + j) * 128 + c4 * 4;
                    asm volatile("cp.async.cg.shared.global [%0], [%1], 16;"
                        :: "r"(xu + (unsigned)((n * XSTR + c4 * 4) * 4)), "l"(src));
                }
            }
            CPA_COMMIT();
        }

        // ---- Phase 1a: bf16 Q,K passes (t=0,1), 16x32 warp tiles, k16 MMA ----
        // fill Xb (bf16 pack of this window's x) once
        for (int idx = tid; idx < NTOK * 64; idx += 512) {
            int n = idx >> 6, c = idx & 63;
            float2 v = *(float2*)(Xs + n * XSTR + 2 * c);
            Xb[n * QBSTR + c] = packbf(v.x, v.y);
        }

        for (int t = 0; t < 2; ++t) {
            // fill Wb: [n][kp] bf16, kp swizzled by (n>>3)&3 (conflict-free STS + frag LDS)
            #pragma unroll 4
            for (int p = 0; p < 16; ++p) {
                int idx = tid + 512 * p;              // 8192 = 128n x 64kp
                int n = idx & 127, kp = idx >> 7;
                float w0 = w_qkv[(long)(2 * kp)     * 384 + t * 128 + n];
                float w1 = w_qkv[(long)(2 * kp + 1) * 384 + t * 128 + n];
                Wb[n * QBSTR + (kp ^ ((n >> 3) & 3))] = packbf(w0, w1);
            }
            __syncthreads();

            float c[4][4];
            #pragma unroll
            for (int i = 0; i < 4; ++i) { c[i][0]=0.f; c[i][1]=0.f; c[i][2]=0.f; c[i][3]=0.f; }

            #pragma unroll
            for (int s = 0; s < 8; ++s) {
                int k0 = s * 8;
                unsigned a[4];
                a[0] = Xb[lA0 * QBSTR + k0 + tig];
                a[1] = Xb[lA1 * QBSTR + k0 + tig];
                a[2] = Xb[lA0 * QBSTR + k0 + tig + 4];
                a[3] = Xb[lA1 * QBSTR + k0 + tig + 4];
                #pragma unroll
                for (int nt = 0; nt < 4; ++nt) {
                    int nb = wxA * 32 + nt * 8 + gid;
                    int sw = (nb >> 3) & 3;
                    unsigned b0 = Wb[nb * QBSTR + ((k0 + tig) ^ sw)];
                    unsigned b1 = Wb[nb * QBSTR + ((k0 + 4 + tig) ^ sw)];
                    mma16(c[nt], a, b0, b1);
                }
            }
            unsigned* dst = (t == 0) ? Qb : Kb;
            #pragma unroll
            for (int nt = 0; nt < 4; ++nt) {
                int col8 = wxA * 32 + nt * 8 + 2 * tig;
                float bb0 = BQ[t * 128 + col8], bb1 = BQ[t * 128 + col8 + 1];
                int bcol = wxA * 16 + nt * 4 + tig;
                if (rA0 < NTOK) dst[rA0 * QBSTR + bcol] = packbf(c[nt][0] + bb0, c[nt][1] + bb1);
                if (rA1 < NTOK) dst[rA1 * QBSTR + bcol] = packbf(c[nt][2] + bb0, c[nt][3] + bb1);
            }
            __syncthreads();
        }

        // ---- Phase 1b: V pass (t=2), tf32, fp32 W tile ----
        {
            #pragma unroll 4
            for (int p = 0; p < 8; ++p) {
                int idx = tid + 512 * p;              // 4096 float4
                int k = idx >> 5, c4 = idx & 31;
                float4 g = *(const float4*)(w_qkv + (long)k * 384 + 256 + c4 * 4);
                g.x = f2tf(g.x); g.y = f2tf(g.y); g.z = f2tf(g.z); g.w = f2tf(g.w);
                *(float4*)(Wsm + k * WSTR + c4 * 4) = g;
            }
            __syncthreads();

            float c[4][4];
            #pragma unroll
            for (int i = 0; i < 4; ++i) { c[i][0]=0.f; c[i][1]=0.f; c[i][2]=0.f; c[i][3]=0.f; }

            #pragma unroll 4
            for (int kk = 0; kk < 16; ++kk) {
                int k0 = kk * 8;
                unsigned a[4];
                a[0] = U(Xs[lA0 * XSTR + k0 + tig]);
                a[1] = U(Xs[lA1 * XSTR + k0 + tig]);
                a[2] = U(Xs[lA0 * XSTR + k0 + tig + 4]);
                a[3] = U(Xs[lA1 * XSTR + k0 + tig + 4]);
                #pragma unroll
                for (int nt = 0; nt < 4; ++nt) {
                    int nb = wxA * 32 + nt * 8 + gid;
                    unsigned b0 = U(Wsm[(k0 + tig) * WSTR + nb]);
                    unsigned b1 = U(Wsm[(k0 + tig + 4) * WSTR + nb]);
                    mma8(c[nt], a, b0, b1);
                }
            }
            #pragma unroll
            for (int nt = 0; nt < 4; ++nt) {
                int col8 = wxA * 32 + nt * 8 + 2 * tig;
                float bb0 = BQ[256 + col8], bb1 = BQ[256 + col8 + 1];
                if (rA0 < NTOK) {
                    float2 v; v.x = f2tf(c[nt][0] + bb0); v.y = f2tf(c[nt][1] + bb1);
                    *(float2*)(Vs + rA0 * VSTR + col8) = v;
                }
                if (rA1 < NTOK) {
                    float2 v; v.x = f2tf(c[nt][2] + bb0); v.y = f2tf(c[nt][3] + bb1);
                    *(float2*)(Vs + rA1 * VSTR + col8) = v;
                }
            }
            __syncthreads();   // Vs visible; Wsm reads done (phase-2 w_proj load may rewrite)
        }

        // ---- Phase 2a: logits = scale * Q K^T + bias (bf16 m16n8k16) ----
        {
            const int qb = hB * 16;
            const int ntmax = wx2 ? 3 : 4;

            const int la0 = m0B + gid;
            const int la1 = m0B + 8 + gid;
            int la2 = m0B + 16 + gid; if (la2 > 48) la2 = 48;
            int la3 = m0B + 24 + gid; if (la3 > 48) la3 = 48;

            float c[2][4][4];
            #pragma unroll
            for (int mt = 0; mt < 2; ++mt)
                #pragma unroll
                for (int i = 0; i < 4; ++i)
                    { c[mt][i][0]=0.f; c[mt][i][1]=0.f; c[mt][i][2]=0.f; c[mt][i][3]=0.f; }

            #pragma unroll
            for (int s = 0; s < 2; ++s) {
                int k0 = s * 8;
                unsigned a0[4], a1[4];
                a0[0] = Qb[la0 * QBSTR + qb + k0 + tig];
                a0[1] = Qb[la1 * QBSTR + qb + k0 + tig];
                a0[2] = Qb[la0 * QBSTR + qb + k0 + tig + 4];
                a0[3] = Qb[la1 * QBSTR + qb + k0 + tig + 4];
                a1[0] = Qb[la2 * QBSTR + qb + k0 + tig];
                a1[1] = Qb[la3 * QBSTR + qb + k0 + tig];
                a1[2] = Qb[la2 * QBSTR + qb + k0 + tig + 4];
                a1[3] = Qb[la3 * QBSTR + qb + k0 + tig + 4];
                for (int nt = 0; nt < ntmax; ++nt) {
                    int nb = wx2 * 32 + nt * 8 + gid;    // rows 49-55 zero
                    unsigned b0 = Kb[nb * QBSTR + qb + k0 + tig];
                    unsigned b1 = Kb[nb * QBSTR + qb + k0 + tig + 4];
                    mma16(c[0][nt], a0, b0, b1);
                    mma16(c[1][nt], a1, b0, b1);
                }
            }

            #pragma unroll
            for (int mt = 0; mt < 2; ++mt) {
                int rs0 = m0B + mt * 16 + gid;
                int rs1 = rs0 + 8;
                int rn0 = rs0 / 7, cn0 = rs0 - rn0 * 7;
                int rn1 = rs1 / 7, cn1 = rs1 - rn1 * 7;
                for (int nt = 0; nt < ntmax; ++nt) {
                    int col  = wx2 * 32 + nt * 8 + 2 * tig;
                    int col1 = col + 1;
                    int rm0 = col / 7,  cm0 = col  - rm0 * 7;
                    int rm1 = col1 / 7, cm1 = col1 - rm1 * 7;
                    if (rs0 < NTOK) {
                        float2 v;
                        v.x = (col  < NTOK) ? c[mt][nt][0] * scale + BT[rn0 - rm0 + 6] + BT[cn0 - cm0 + 6] : 0.f;
                        v.y = (col1 < NTOK) ? c[mt][nt][1] * scale + BT[rn0 - rm1 + 6] + BT[cn0 - cm1 + 6] : 0.f;
                        *(float2*)(Lh + rs0 * LSTR + col) = v;
                    }
                    if (rs1 < NTOK) {
                        float2 v;
                        v.x = (col  < NTOK) ? c[mt][nt][2] * scale + BT[rn1 - rm0 + 6] + BT[cn1 - cm0 + 6] : 0.f;
                        v.y = (col1 < NTOK) ? c[mt][nt][3] * scale + BT[rn1 - rm1 + 6] + BT[cn1 - cm1 + 6] : 0.f;
                        *(float2*)(Lh + rs1 * LSTR + col) = v;
                    }
                }
            }
        }

        // overlap: this head group loads its quarter of w_proj into Wsm
        {
            const int wg_tid = tid & 127;
            for (int idx = wg_tid; idx < 32 * 32; idx += 128) {
                int row = hB * 32 + (idx >> 5);
                int c4  = idx & 31;
                float4 g = *(const float4*)(w_proj + (long)row * 128 + c4 * 4);
                g.x = f2tf(g.x); g.y = f2tf(g.y); g.z = f2tf(g.z); g.w = f2tf(g.w);
                *(float4*)(Wsm + row * WSTR + c4 * 4) = g;
            }
        }
        HBAR();

        // ---- Phase 2b: max-free softmax (logits bounded; exp safe) ----
        for (int row = lw; row < NTOK; row += 4) {
            float e0 = __expf(Lh[row * LSTR + tx]);
            float e1 = (tx + 32 < NTOK) ? __expf(Lh[row * LSTR + tx + 32]) : 0.f;
            float s = e0 + e1;
            #pragma unroll
            for (int o = 16; o > 0; o >>= 1)
                s += __shfl_xor_sync(0xffffffffu, s, o);
            float inv = 1.0f / s;
            Lh[row * LSTR + tx] = f2tf(e0 * inv);
            if (tx + 32 < NTOK) Lh[row * LSTR + tx + 32] = f2tf(e1 * inv);
        }
        HBAR();

        // ---- Phase 2c: out_h = attn @ V (tf32; M=64 N=32 K=56) ----
        {
            const int la0 = m0B + gid;
            const int la1 = m0B + 8 + gid;
            int la2 = m0B + 16 + gid; if (la2 > 48) la2 = 48;
            int la3 = m0B + 24 + gid; if (la3 > 48) la3 = 48;

            float c[2][2][4];
            #pragma unroll
            for (int mt = 0; mt < 2; ++mt)
                #pragma unroll
                for (int i = 0; i < 2; ++i)
                    { c[mt][i][0]=0.f; c[mt][i][1]=0.f; c[mt][i][2]=0.f; c[mt][i][3]=0.f; }

            #pragma unroll
            for (int ks = 0; ks < 7; ++ks) {
                int k0 = ks * 8;
                unsigned a0[4], a1[4];
                a0[0] = U(Lh[la0 * LSTR + k0 + tig]);
                a0[1] = U(Lh[la1 * LSTR + k0 + tig]);
                a0[2] = U(Lh[la0 * LSTR + k0 + tig + 4]);
                a0[3] = U(Lh[la1 * LSTR + k0 + tig + 4]);
                a1[0] = U(Lh[la2 * LSTR + k0 + tig]);
                a1[1] = U(Lh[la3 * LSTR + k0 + tig]);
                a1[2] = U(Lh[la2 * LSTR + k0 + tig + 4]);
                a1[3] = U(Lh[la3 * LSTR + k0 + tig + 4]);
                #pragma unroll
                for (int nt = 0; nt < 2; ++nt) {
                    int db = qo + wx2 * 16 + nt * 8 + gid;
                    unsigned b0 = U(Vs[(k0 + tig) * VSTR + db]);
                    unsigned b1 = U(Vs[(k0 + tig + 4) * VSTR + db]);
                    mma8(c[0][nt], a0, b0, b1);
                    mma8(c[1][nt], a1, b0, b1);
                }
            }
            #pragma unroll
            for (int mt = 0; mt < 2; ++mt) {
                int rs0 = m0B + mt * 16 + gid;
                int rs1 = rs0 + 8;
                #pragma unroll
                for (int nt = 0; nt < 2; ++nt) {
                    int col = qo + wx2 * 16 + nt * 8 + 2 * tig;
                    if (rs0 < NTOK) {
                        float2 v; v.x = f2tf(c[mt][nt][0]); v.y = f2tf(c[mt][nt][1]);
                        *(float2*)(Xs + rs0 * XSTR + col) = v;
                    }
                    if (rs1 < NTOK) {
                        float2 v; v.x = f2tf(c[mt][nt][2]); v.y = f2tf(c[mt][nt][3]);
                        *(float2*)(Xs + rs1 * XSTR + col) = v;
                    }
                }
            }
        }
        __syncthreads();

        // ---- Phase 3: proj GEMM (Wsm loaded during phase 2), store ----
        {
            float c[4][4];
            #pragma unroll
            for (int i = 0; i < 4; ++i) { c[i][0]=0.f; c[i][1]=0.f; c[i][2]=0.f; c[i][3]=0.f; }

            #pragma unroll 4
            for (int kk = 0; kk < 16; ++kk) {
                int k0 = kk * 8;
                unsigned a[4];
                a[0] = U(Xs[lA0 * XSTR + k0 + tig]);
                a[1] = U(Xs[lA1 * XSTR + k0 + tig]);
                a[2] = U(Xs[lA0 * XSTR + k0 + tig + 4]);
                a[3] = U(Xs[lA1 * XSTR + k0 + tig + 4]);
                #pragma unroll
                for (int nt = 0; nt < 4; ++nt) {
                    int nb = wxA * 32 + nt * 8 + gid;
                    unsigned b0 = U(Wsm[(k0 + tig) * WSTR + nb]);
                    unsigned b1 = U(Wsm[(k0 + tig + 4) * WSTR + nb]);
                    mma8(c[nt], a, b0, b1);
                }
            }

            long base0 = 0, base1 = 0;
            if (rA0 < NTOK) {
                int i = rA0 / 7, j = rA0 - (rA0 / 7) * 7;
                base0 = (((long)bz * HW + wh * WSZ + i) * HW + ww * WSZ + j) * 128;
            }
            if (rA1 < NTOK) {
                int i = rA1 / 7, j = rA1 - (rA1 / 7) * 7;
                base1 = (((long)bz * HW + wh * WSZ + i) * HW + ww * WSZ + j) * 128;
            }
            #pragma unroll
            for (int nt = 0; nt < 4; ++nt) {
                int col = wxA * 32 + nt * 8 + 2 * tig;
                float bb0 = BP[col], bb1 = BP[col + 1];
                if (rA0 < NTOK) {
                    float2 v; v.x = c[nt][0] + bb0; v.y = c[nt][1] + bb1;
                    *(float2*)(out + base0 + col) = v;
                }
                if (rA1 < NTOK) {
                    float2 v; v.x = c[nt][2] + bb0; v.y = c[nt][3] + bb1;
                    *(float2*)(out + base1 + col) = v;
                }
            }
        }
    }
}

extern "C" void kernel_launch(void* const* d_in, const int* in_sizes, int n_in,
                              void* d_out, int out_size) {
    const float* x          = (const float*)d_in[0];
    const float* w_qkv      = (const float*)d_in[1];
    const float* b_qkv      = (const float*)d_in[2];
    const float* w_proj     = (const float*)d_in[3];
    const float* b_proj     = (const float*)d_in[4];
    const float* bias_table = (const float*)d_in[5];
    float* out = (float*)d_out;
    (void)in_sizes; (void)n_in; (void)out_size;

    cudaFuncSetAttribute(win_attn_bfw_kernel,
                         cudaFuncAttributeMaxDynamicSharedMemorySize, SMEM_BYTES);

    win_attn_bfw_kernel<<<GRID, 512, SMEM_BYTES>>>(
        x, w_qkv, b_qkv, w_proj, b_proj, bias_table, out);
}